// round 11
// baseline (speedup 1.0000x reference)
#include <cuda_runtime.h>
#include <cuda_bf16.h>
#include <math.h>

#define SEQ   8192
#define DIM   2048
#define H     16
#define HD    128      // head dim
#define PROJ  512
#define LSPLIT 4       // K splits for logits
#define LKR   (DIM / LSPLIT)        // 512
#define LROWS 8        // rows per block in k_logits
#define YSPLIT 128     // seq splits for y
#define YROWS (SEQ / YSPLIT)        // 64
#define INV_SQRT_D 0.08838834764831843f

typedef unsigned long long u64;

// ---------------- scratch (device globals; no allocation allowed) ----------------
__device__ float g_u[H * DIM];                 // folded query
__device__ float g_c[H];                       // bias logit
__device__ float g_lpart[LSPLIT][H][SEQ];      // logit partials over K splits
__device__ float g_p[H * SEQ];                 // normalized softmax weights
__device__ float g_ypart[YSPLIT][H * DIM];     // y partials over seq splits (16 MB)
__device__ float g_y[H * DIM];
__device__ float g_x1[DIM];
__device__ float g_h1[PROJ];
__device__ float g_h1n[PROJ];
__device__ float g_x2[DIM];

// ---------------- f32x2 packed helpers ----------------
__device__ __forceinline__ u64 pack2(float lo, float hi) {
    u64 r; asm("mov.b64 %0, {%1, %2};" : "=l"(r) : "f"(lo), "f"(hi)); return r;
}
__device__ __forceinline__ void unpack2(u64 v, float& lo, float& hi) {
    asm("mov.b64 {%0, %1}, %2;" : "=f"(lo), "=f"(hi) : "l"(v));
}
__device__ __forceinline__ void fma2(u64& d, u64 a, u64 b) {
    asm("fma.rn.f32x2 %0, %1, %2, %3;" : "=l"(d) : "l"(a), "l"(b), "l"(d));
}

// ---------------- helpers ----------------
__device__ __forceinline__ float blk_reduce(float val, bool is_max, float* red) {
    int l = threadIdx.x & 31, w = threadIdx.x >> 5;
    #pragma unroll
    for (int o = 16; o; o >>= 1) {
        float ov = __shfl_xor_sync(0xffffffffu, val, o);
        val = is_max ? fmaxf(val, ov) : (val + ov);
    }
    if (l == 0) red[w] = val;
    __syncthreads();
    int nw = blockDim.x >> 5;
    if (w == 0) {
        float v2 = (l < nw) ? red[l] : (is_max ? -INFINITY : 0.f);
        #pragma unroll
        for (int o = 16; o; o >>= 1) {
            float ov = __shfl_xor_sync(0xffffffffu, v2, o);
            v2 = is_max ? fmaxf(v2, ov) : (v2 + ov);
        }
        if (l == 0) red[0] = v2;
    }
    __syncthreads();
    float r = red[0];
    __syncthreads();
    return r;
}

// ---------------- k_u: u[h][col] = sum_j q[h*HD+j] * W_kv[h*HD+j][col]
__global__ __launch_bounds__(256) void k_u(const float* __restrict__ q,
                                           const float* __restrict__ W_kv,
                                           const float* __restrict__ b_kv) {
    int h = blockIdx.x, t = threadIdx.x;
    __shared__ float qs[HD];
    if (t < HD) qs[t] = q[h * HD + t];
    __syncthreads();
    int col = blockIdx.y * 256 + t;
    const float* W = W_kv + (size_t)h * HD * DIM + col;
    float acc = 0.f;
    #pragma unroll 8
    for (int j = 0; j < HD; j++) acc += qs[j] * W[(size_t)j * DIM];
    g_u[h * DIM + col] = acc;

    if (blockIdx.y == 0 && t < 32) {
        float cc = 0.f;
        for (int j = t; j < HD; j += 32) cc += qs[j] * b_kv[h * HD + j];
        #pragma unroll
        for (int o = 16; o; o >>= 1) cc += __shfl_xor_sync(0xffffffffu, cc, o);
        if (t == 0) g_c[h] = cc;
    }
}

// ---------------- k_logits: f32x2 packed, warp-per-2-rows.
// block 128 (4 warps -> 8 rows/block), grid (SEQ/8, LSPLIT). u chunk (16x512) in smem.
__global__ __launch_bounds__(128) void k_logits(const float* __restrict__ x) {
    __shared__ ulonglong2 us2[H][LKR / 4];   // 32 KB
    int t = threadIdx.x, l = t & 31, w = t >> 5;
    int k0f4 = blockIdx.y * (LKR / 4);
    for (int i = t; i < H * (LKR / 4); i += 128) {
        int h = i >> 7, kk = i & 127;   // LKR/4 = 128
        us2[h][kk] = ((const ulonglong2*)g_u)[h * (DIM / 4) + k0f4 + kk];
    }
    __syncthreads();
    int row0 = blockIdx.x * LROWS + w * 2;
    u64 acc[2][H];
    #pragma unroll
    for (int r = 0; r < 2; r++)
        #pragma unroll
        for (int h = 0; h < H; h++) acc[r][h] = pack2(0.f, 0.f);
    const ulonglong2* xr = (const ulonglong2*)x;
    #pragma unroll
    for (int kc = 0; kc < LKR / 4; kc += 32) {
        int kidx = kc + l;
        ulonglong2 xv0 = xr[(size_t)(row0    ) * (DIM / 4) + k0f4 + kidx];
        ulonglong2 xv1 = xr[(size_t)(row0 + 1) * (DIM / 4) + k0f4 + kidx];
        #pragma unroll
        for (int h = 0; h < H; h++) {
            ulonglong2 uv = us2[h][kidx];
            fma2(acc[0][h], xv0.x, uv.x);
            fma2(acc[0][h], xv0.y, uv.y);
            fma2(acc[1][h], xv1.x, uv.x);
            fma2(acc[1][h], xv1.y, uv.y);
        }
    }
    #pragma unroll
    for (int r = 0; r < 2; r++)
        #pragma unroll
        for (int h = 0; h < H; h++) {
            float a, b;
            unpack2(acc[r][h], a, b);
            float v = a + b;
            #pragma unroll
            for (int o = 16; o; o >>= 1) v += __shfl_xor_sync(0xffffffffu, v, o);
            if (l == 0) g_lpart[blockIdx.y][h][row0 + r] = v;
        }
}

// ---------------- k_softmax: per head. grid 16, block 1024 (8 values/thread)
__global__ __launch_bounds__(1024) void k_softmax() {
    int h = blockIdx.x, t = threadIdx.x;
    __shared__ float red[32];
    float ch = g_c[h];
    float v[8];
    #pragma unroll
    for (int ii = 0; ii < 8; ii++) {
        int s = t + ii * 1024;
        float sum = 0.f;
        #pragma unroll
        for (int p = 0; p < LSPLIT; p++) sum += g_lpart[p][h][s];
        v[ii] = (sum + ch) * INV_SQRT_D;
    }
    float m = v[0];
    #pragma unroll
    for (int ii = 1; ii < 8; ii++) m = fmaxf(m, v[ii]);
    m = blk_reduce(m, true, red);
    float lsum = 0.f;
    #pragma unroll
    for (int ii = 0; ii < 8; ii++) { v[ii] = __expf(v[ii] - m); lsum += v[ii]; }
    float tot = blk_reduce(lsum, false, red);
    float inv = 1.f / tot;
    #pragma unroll
    for (int ii = 0; ii < 8; ii++) g_p[h * SEQ + t + ii * 1024] = v[ii] * inv;
}

// ---------------- k_y: f32x2 packed streaming. One float4 column + 16 head accs per thread.
// block 256, grid (2, YSPLIT = 128). p staged pre-packed (p,p) in smem.
__global__ __launch_bounds__(256) void k_y(const float* __restrict__ x) {
    __shared__ u64 ps2[YROWS][H];       // 8 KB, (p,p) packed
    int t = threadIdx.x;
    int c4 = blockIdx.x * 256 + t;      // float4 column, 0..511
    int sp = blockIdx.y;
    int s0 = sp * YROWS;
    for (int i = t; i < YROWS * H; i += 256) {
        int r = i >> 4, h = i & 15;
        float p = g_p[h * SEQ + s0 + r];
        ps2[r][h] = pack2(p, p);
    }
    __syncthreads();
    u64 acc[H][2];
    #pragma unroll
    for (int h = 0; h < H; h++) { acc[h][0] = pack2(0.f, 0.f); acc[h][1] = acc[h][0]; }
    const ulonglong2* xr = (const ulonglong2*)x;
    #pragma unroll 4
    for (int r = 0; r < YROWS; r++) {
        ulonglong2 xv = xr[(size_t)(s0 + r) * (DIM / 4) + c4];
        #pragma unroll
        for (int hp = 0; hp < 8; hp++) {
            ulonglong2 pv = *((const ulonglong2*)&ps2[r][hp * 2]);
            fma2(acc[2*hp  ][0], pv.x, xv.x);
            fma2(acc[2*hp  ][1], pv.x, xv.y);
            fma2(acc[2*hp+1][0], pv.y, xv.x);
            fma2(acc[2*hp+1][1], pv.y, xv.y);
        }
    }
    ulonglong2* yp = (ulonglong2*)g_ypart[sp];
    #pragma unroll
    for (int h = 0; h < H; h++)
        yp[h * (DIM / 4) + c4] = make_ulonglong2(acc[h][0], acc[h][1]);
}

// ---------------- k_ysum: y[e4] = sum over YSPLIT partials (float4). grid 32, block 256
__global__ __launch_bounds__(256) void k_ysum() {
    int e4 = blockIdx.x * 256 + threadIdx.x;     // float4 index, 0..8191
    float4 s = make_float4(0.f, 0.f, 0.f, 0.f);
    #pragma unroll
    for (int p = 0; p < YSPLIT; p++) {
        float4 v = ((const float4*)g_ypart[p])[e4];
        s.x += v.x; s.y += v.y; s.z += v.z; s.w += v.w;
    }
    ((float4*)g_y)[e4] = s;
}

// ---------------- k_x1: x1[j] = W_v row j . y_h + b. float4 loads. grid 256, block 256
__global__ __launch_bounds__(256) void k_x1(const float* __restrict__ W_kv,
                                            const float* __restrict__ b_kv) {
    int w = threadIdx.x >> 5, l = threadIdx.x & 31;
    int j = blockIdx.x * 8 + w;
    int h = j >> 7;
    const float4* W4 = (const float4*)(W_kv + (size_t)(DIM + j) * DIM);
    const float4* y4 = (const float4*)(g_y + h * DIM);
    float s = 0.f;
    #pragma unroll
    for (int i = l; i < DIM / 4; i += 32) {
        float4 a = W4[i], b = y4[i];
        s += a.x * b.x + a.y * b.y + a.z * b.z + a.w * b.w;
    }
    #pragma unroll
    for (int o = 16; o; o >>= 1) s += __shfl_xor_sync(0xffffffffu, s, o);
    if (l == 0) g_x1[j] = s + b_kv[DIM + j];
}

// ---------------- k_mlp1: float4 loads
__global__ __launch_bounds__(256) void k_mlp1(const float* __restrict__ W_p1,
                                              const float* __restrict__ b_p1) {
    int w = threadIdx.x >> 5, l = threadIdx.x & 31;
    int j = blockIdx.x * 8 + w;
    const float4* W4 = (const float4*)(W_p1 + (size_t)j * DIM);
    const float4* x4 = (const float4*)g_x1;
    float s = 0.f;
    #pragma unroll
    for (int i = l; i < DIM / 4; i += 32) {
        float4 a = W4[i], b = x4[i];
        s += a.x * b.x + a.y * b.y + a.z * b.z + a.w * b.w;
    }
    #pragma unroll
    for (int o = 16; o; o >>= 1) s += __shfl_xor_sync(0xffffffffu, s, o);
    if (l == 0) g_h1[j] = s + b_p1[j];
}

// ---------------- k_ln: LayerNorm + ReLU
__global__ __launch_bounds__(512) void k_ln(const float* __restrict__ ln_w,
                                            const float* __restrict__ ln_b) {
    __shared__ float red[32];
    int t = threadIdx.x;
    float hv = g_h1[t];
    float mean = blk_reduce(hv, false, red) * (1.f / PROJ);
    float d = hv - mean;
    float var = blk_reduce(d * d, false, red) * (1.f / PROJ);
    float r = d * rsqrtf(var + 1e-5f) * ln_w[t] + ln_b[t];
    g_h1n[t] = fmaxf(0.f, r);
}

// ---------------- k_mlp2: float4 loads
__global__ __launch_bounds__(256) void k_mlp2(const float* __restrict__ W_p2,
                                              const float* __restrict__ b_p2) {
    int w = threadIdx.x >> 5, l = threadIdx.x & 31;
    int j = blockIdx.x * 8 + w;
    const float4* W4 = (const float4*)(W_p2 + (size_t)j * PROJ);
    const float4* h4 = (const float4*)g_h1n;
    float s = 0.f;
    #pragma unroll
    for (int i = l; i < PROJ / 4; i += 32) {
        float4 a = W4[i], b = h4[i];
        s += a.x * b.x + a.y * b.y + a.z * b.z + a.w * b.w;
    }
    #pragma unroll
    for (int o = 16; o; o >>= 1) s += __shfl_xor_sync(0xffffffffu, s, o);
    if (l == 0) g_x2[j] = s + b_p2[j];
}

// ---------------- k_res: out = x + broadcast(x2). 2 float4/thread. grid 8192, block 256
__global__ __launch_bounds__(256) void k_res(const float* __restrict__ x,
                                             float* __restrict__ out) {
    int i0 = blockIdx.x * 512 + threadIdx.x;
    #pragma unroll
    for (int rep = 0; rep < 2; rep++) {
        int i = i0 + rep * 256;
        const float4 a = ((const float4*)x)[i];
        const float4 b = ((const float4*)g_x2)[i & 511];
        float4 r; r.x = a.x + b.x; r.y = a.y + b.y; r.z = a.z + b.z; r.w = a.w + b.w;
        ((float4*)out)[i] = r;
    }
}

// ---------------- launch ----------------
extern "C" void kernel_launch(void* const* d_in, const int* in_sizes, int n_in,
                              void* d_out, int out_size) {
    const float* x    = (const float*)d_in[0];
    const float* q    = (const float*)d_in[1];
    const float* W_kv = (const float*)d_in[2];
    const float* b_kv = (const float*)d_in[3];
    const float* W_p1 = (const float*)d_in[4];
    const float* b_p1 = (const float*)d_in[5];
    const float* W_p2 = (const float*)d_in[6];
    const float* b_p2 = (const float*)d_in[7];
    const float* ln_w = (const float*)d_in[8];
    const float* ln_b = (const float*)d_in[9];
    float* out = (float*)d_out;

    k_u      <<<dim3(H, DIM / 256), 256>>>(q, W_kv, b_kv);
    k_logits <<<dim3(SEQ / LROWS, LSPLIT), 128>>>(x);
    k_softmax<<<H, 1024>>>();
    k_y      <<<dim3(2, YSPLIT), 256>>>(x);
    k_ysum   <<<(H * DIM / 4) / 256, 256>>>();
    k_x1     <<<DIM / 8, 256>>>(W_kv, b_kv);
    k_mlp1   <<<PROJ / 8, 256>>>(W_p1, b_p1);
    k_ln     <<<1, PROJ>>>(ln_w, ln_b);
    k_mlp2   <<<DIM / 8, 256>>>(W_p2, b_p2);
    k_res    <<<(SEQ * DIM / 4) / 512, 256>>>(x, out);
}

// round 12
// speedup vs baseline: 1.1871x; 1.1871x over previous
#include <cuda_runtime.h>
#include <cuda_bf16.h>
#include <math.h>

#define SEQ   8192
#define DIM   2048
#define H     16
#define HD    128      // head dim
#define PROJ  512
#define LSPLIT 4       // K splits for logits
#define LKR   (DIM / LSPLIT)        // 512
#define YSPLIT 128     // seq splits for y
#define YROWS (SEQ / YSPLIT)        // 64
#define INV_SQRT_D 0.08838834764831843f

// ---------------- scratch (device globals; no allocation allowed) ----------------
__device__ float g_u[H * DIM];                 // folded query
__device__ float g_c[H];                       // bias logit
__device__ float g_lpart[LSPLIT][H][SEQ];      // logit partials over K splits
__device__ float g_p[H * SEQ];                 // normalized softmax weights
__device__ float g_ypart[YSPLIT][H * DIM];     // y partials over seq splits (16 MB)
__device__ float g_y[H * DIM];
__device__ float g_x1[DIM];
__device__ float g_h1[PROJ];
__device__ float g_h1n[PROJ];
__device__ float g_x2[DIM];

// ---------------- helpers ----------------
__device__ __forceinline__ float blk_reduce(float val, bool is_max, float* red) {
    int l = threadIdx.x & 31, w = threadIdx.x >> 5;
    #pragma unroll
    for (int o = 16; o; o >>= 1) {
        float ov = __shfl_xor_sync(0xffffffffu, val, o);
        val = is_max ? fmaxf(val, ov) : (val + ov);
    }
    if (l == 0) red[w] = val;
    __syncthreads();
    int nw = blockDim.x >> 5;
    if (w == 0) {
        float v2 = (l < nw) ? red[l] : (is_max ? -INFINITY : 0.f);
        #pragma unroll
        for (int o = 16; o; o >>= 1) {
            float ov = __shfl_xor_sync(0xffffffffu, v2, o);
            v2 = is_max ? fmaxf(v2, ov) : (v2 + ov);
        }
        if (l == 0) red[0] = v2;
    }
    __syncthreads();
    float r = red[0];
    __syncthreads();
    return r;
}

// ---------------- k_u: u[h][col] = sum_j q[h*HD+j] * W_kv[h*HD+j][col]
__global__ __launch_bounds__(256) void k_u(const float* __restrict__ q,
                                           const float* __restrict__ W_kv,
                                           const float* __restrict__ b_kv) {
    int h = blockIdx.x, t = threadIdx.x;
    __shared__ float qs[HD];
    if (t < HD) qs[t] = q[h * HD + t];
    __syncthreads();
    int col = blockIdx.y * 256 + t;
    const float* W = W_kv + (size_t)h * HD * DIM + col;
    float acc = 0.f;
    #pragma unroll 8
    for (int j = 0; j < HD; j++) acc += qs[j] * W[(size_t)j * DIM];
    g_u[h * DIM + col] = acc;

    if (blockIdx.y == 0 && t < 32) {
        float cc = 0.f;
        for (int j = t; j < HD; j += 32) cc += qs[j] * b_kv[h * HD + j];
        #pragma unroll
        for (int o = 16; o; o >>= 1) cc += __shfl_xor_sync(0xffffffffu, cc, o);
        if (t == 0) g_c[h] = cc;
    }
}

// ---------------- k_logits: streaming warp-per-4-rows (R8 config — measured good).
// block 256 (8 warps -> 32 rows/block), grid (SEQ/32, LSPLIT). u chunk (16x512) in smem.
__global__ __launch_bounds__(256) void k_logits(const float* __restrict__ x) {
    __shared__ float4 us[H][LKR / 4];   // 32 KB
    int t = threadIdx.x, l = t & 31, w = t >> 5;
    int k0f4 = blockIdx.y * (LKR / 4);
    for (int i = t; i < H * (LKR / 4); i += 256) {
        int h = i >> 7, kk = i & 127;   // LKR/4 = 128
        us[h][kk] = ((const float4*)g_u)[h * (DIM / 4) + k0f4 + kk];
    }
    __syncthreads();
    int row0 = blockIdx.x * 32 + w * 4;
    float acc[4][H];
    #pragma unroll
    for (int r = 0; r < 4; r++)
        #pragma unroll
        for (int h = 0; h < H; h++) acc[r][h] = 0.f;
    const float4* xr = (const float4*)x;
    #pragma unroll
    for (int kc = 0; kc < LKR / 4; kc += 32) {
        int kidx = kc + l;
        float4 xv[4];
        #pragma unroll
        for (int r = 0; r < 4; r++)
            xv[r] = xr[(size_t)(row0 + r) * (DIM / 4) + k0f4 + kidx];
        #pragma unroll
        for (int h = 0; h < H; h++) {
            float4 uv = us[h][kidx];
            #pragma unroll
            for (int r = 0; r < 4; r++)
                acc[r][h] += xv[r].x * uv.x + xv[r].y * uv.y
                           + xv[r].z * uv.z + xv[r].w * uv.w;
        }
    }
    #pragma unroll
    for (int r = 0; r < 4; r++)
        #pragma unroll
        for (int h = 0; h < H; h++) {
            float v = acc[r][h];
            #pragma unroll
            for (int o = 16; o; o >>= 1) v += __shfl_xor_sync(0xffffffffu, v, o);
            if (l == 0) g_lpart[blockIdx.y][h][row0 + r] = v;
        }
}

// ---------------- k_softmax: per head. grid 16, block 1024 (8 values/thread)
__global__ __launch_bounds__(1024) void k_softmax() {
    int h = blockIdx.x, t = threadIdx.x;
    __shared__ float red[32];
    float ch = g_c[h];
    float v[8];
    #pragma unroll
    for (int ii = 0; ii < 8; ii++) {
        int s = t + ii * 1024;
        float sum = 0.f;
        #pragma unroll
        for (int p = 0; p < LSPLIT; p++) sum += g_lpart[p][h][s];
        v[ii] = (sum + ch) * INV_SQRT_D;
    }
    float m = v[0];
    #pragma unroll
    for (int ii = 1; ii < 8; ii++) m = fmaxf(m, v[ii]);
    m = blk_reduce(m, true, red);
    float lsum = 0.f;
    #pragma unroll
    for (int ii = 0; ii < 8; ii++) { v[ii] = __expf(v[ii] - m); lsum += v[ii]; }
    float tot = blk_reduce(lsum, false, red);
    float inv = 1.f / tot;
    #pragma unroll
    for (int ii = 0; ii < 8; ii++) g_p[h * SEQ + t + ii * 1024] = v[ii] * inv;
}

// ---------------- k_y: R6 config (measured 22.8us). One float4 column + 16 head accs.
// block 256, grid (2, YSPLIT = 128). p tile transposed to [row][head] in smem.
__global__ __launch_bounds__(256) void k_y(const float* __restrict__ x) {
    __shared__ float ps[YROWS][H];      // 4 KB
    int t = threadIdx.x;
    int c4 = blockIdx.x * 256 + t;      // float4 column, 0..511
    int sp = blockIdx.y;
    int s0 = sp * YROWS;
    for (int i = t; i < YROWS * H; i += 256) {
        int r = i >> 4, h = i & 15;
        ps[r][h] = g_p[h * SEQ + s0 + r];
    }
    __syncthreads();
    float4 acc[H];
    #pragma unroll
    for (int h = 0; h < H; h++) acc[h] = make_float4(0.f, 0.f, 0.f, 0.f);
    const float4* xr = (const float4*)x;
    #pragma unroll 4
    for (int r = 0; r < YROWS; r++) {
        float4 xv = xr[(size_t)(s0 + r) * (DIM / 4) + c4];
        #pragma unroll
        for (int hq = 0; hq < 4; hq++) {
            float4 pv = *((const float4*)&ps[r][hq * 4]);
            acc[hq*4+0].x += pv.x * xv.x; acc[hq*4+0].y += pv.x * xv.y;
            acc[hq*4+0].z += pv.x * xv.z; acc[hq*4+0].w += pv.x * xv.w;
            acc[hq*4+1].x += pv.y * xv.x; acc[hq*4+1].y += pv.y * xv.y;
            acc[hq*4+1].z += pv.y * xv.z; acc[hq*4+1].w += pv.y * xv.w;
            acc[hq*4+2].x += pv.z * xv.x; acc[hq*4+2].y += pv.z * xv.y;
            acc[hq*4+2].z += pv.z * xv.z; acc[hq*4+2].w += pv.z * xv.w;
            acc[hq*4+3].x += pv.w * xv.x; acc[hq*4+3].y += pv.w * xv.y;
            acc[hq*4+3].z += pv.w * xv.z; acc[hq*4+3].w += pv.w * xv.w;
        }
    }
    float4* yp = (float4*)g_ypart[sp];
    #pragma unroll
    for (int h = 0; h < H; h++)
        yp[h * (DIM / 4) + c4] = acc[h];
}

// ---------------- k_ysum: 4 threads per float4 element, each sums 32 partials.
// block 256 = 64 elements x 4 quarters. grid 128.
__global__ __launch_bounds__(256) void k_ysum() {
    __shared__ float4 red[256];
    int t = threadIdx.x;
    int eloc = t & 63, q = t >> 6;               // element-in-block, quarter
    int e4 = blockIdx.x * 64 + eloc;             // float4 index, 0..8191
    float4 s = make_float4(0.f, 0.f, 0.f, 0.f);
    #pragma unroll
    for (int p = q * 32; p < q * 32 + 32; p++) {
        float4 v = ((const float4*)g_ypart[p])[e4];
        s.x += v.x; s.y += v.y; s.z += v.z; s.w += v.w;
    }
    red[q * 64 + eloc] = s;
    __syncthreads();
    if (q == 0) {
        float4 a = red[eloc], b = red[64 + eloc], c = red[128 + eloc], d = red[192 + eloc];
        float4 r;
        r.x = (a.x + b.x) + (c.x + d.x);
        r.y = (a.y + b.y) + (c.y + d.y);
        r.z = (a.z + b.z) + (c.z + d.z);
        r.w = (a.w + b.w) + (c.w + d.w);
        ((float4*)g_y)[e4] = r;
    }
}

// ---------------- k_x1: x1[j] = W_v row j . y_h + b. float4 loads. grid 256, block 256
__global__ __launch_bounds__(256) void k_x1(const float* __restrict__ W_kv,
                                            const float* __restrict__ b_kv) {
    int w = threadIdx.x >> 5, l = threadIdx.x & 31;
    int j = blockIdx.x * 8 + w;
    int h = j >> 7;
    const float4* W4 = (const float4*)(W_kv + (size_t)(DIM + j) * DIM);
    const float4* y4 = (const float4*)(g_y + h * DIM);
    float s = 0.f;
    #pragma unroll
    for (int i = l; i < DIM / 4; i += 32) {
        float4 a = W4[i], b = y4[i];
        s += a.x * b.x + a.y * b.y + a.z * b.z + a.w * b.w;
    }
    #pragma unroll
    for (int o = 16; o; o >>= 1) s += __shfl_xor_sync(0xffffffffu, s, o);
    if (l == 0) g_x1[j] = s + b_kv[DIM + j];
}

// ---------------- k_mlp1: float4 loads
__global__ __launch_bounds__(256) void k_mlp1(const float* __restrict__ W_p1,
                                              const float* __restrict__ b_p1) {
    int w = threadIdx.x >> 5, l = threadIdx.x & 31;
    int j = blockIdx.x * 8 + w;
    const float4* W4 = (const float4*)(W_p1 + (size_t)j * DIM);
    const float4* x4 = (const float4*)g_x1;
    float s = 0.f;
    #pragma unroll
    for (int i = l; i < DIM / 4; i += 32) {
        float4 a = W4[i], b = x4[i];
        s += a.x * b.x + a.y * b.y + a.z * b.z + a.w * b.w;
    }
    #pragma unroll
    for (int o = 16; o; o >>= 1) s += __shfl_xor_sync(0xffffffffu, s, o);
    if (l == 0) g_h1[j] = s + b_p1[j];
}

// ---------------- k_ln: LayerNorm + ReLU
__global__ __launch_bounds__(512) void k_ln(const float* __restrict__ ln_w,
                                            const float* __restrict__ ln_b) {
    __shared__ float red[32];
    int t = threadIdx.x;
    float hv = g_h1[t];
    float mean = blk_reduce(hv, false, red) * (1.f / PROJ);
    float d = hv - mean;
    float var = blk_reduce(d * d, false, red) * (1.f / PROJ);
    float r = d * rsqrtf(var + 1e-5f) * ln_w[t] + ln_b[t];
    g_h1n[t] = fmaxf(0.f, r);
}

// ---------------- k_mlp2: float4 loads
__global__ __launch_bounds__(256) void k_mlp2(const float* __restrict__ W_p2,
                                              const float* __restrict__ b_p2) {
    int w = threadIdx.x >> 5, l = threadIdx.x & 31;
    int j = blockIdx.x * 8 + w;
    const float4* W4 = (const float4*)(W_p2 + (size_t)j * PROJ);
    const float4* h4 = (const float4*)g_h1n;
    float s = 0.f;
    #pragma unroll
    for (int i = l; i < PROJ / 4; i += 32) {
        float4 a = W4[i], b = h4[i];
        s += a.x * b.x + a.y * b.y + a.z * b.z + a.w * b.w;
    }
    #pragma unroll
    for (int o = 16; o; o >>= 1) s += __shfl_xor_sync(0xffffffffu, s, o);
    if (l == 0) g_x2[j] = s + b_p2[j];
}

// ---------------- k_res: out = x + broadcast(x2). 2 float4/thread. grid 8192, block 256
__global__ __launch_bounds__(256) void k_res(const float* __restrict__ x,
                                             float* __restrict__ out) {
    int i0 = blockIdx.x * 512 + threadIdx.x;
    #pragma unroll
    for (int rep = 0; rep < 2; rep++) {
        int i = i0 + rep * 256;
        const float4 a = ((const float4*)x)[i];
        const float4 b = ((const float4*)g_x2)[i & 511];
        float4 r; r.x = a.x + b.x; r.y = a.y + b.y; r.z = a.z + b.z; r.w = a.w + b.w;
        ((float4*)out)[i] = r;
    }
}

// ---------------- launch ----------------
extern "C" void kernel_launch(void* const* d_in, const int* in_sizes, int n_in,
                              void* d_out, int out_size) {
    const float* x    = (const float*)d_in[0];
    const float* q    = (const float*)d_in[1];
    const float* W_kv = (const float*)d_in[2];
    const float* b_kv = (const float*)d_in[3];
    const float* W_p1 = (const float*)d_in[4];
    const float* b_p1 = (const float*)d_in[5];
    const float* W_p2 = (const float*)d_in[6];
    const float* b_p2 = (const float*)d_in[7];
    const float* ln_w = (const float*)d_in[8];
    const float* ln_b = (const float*)d_in[9];
    float* out = (float*)d_out;

    k_u      <<<dim3(H, DIM / 256), 256>>>(q, W_kv, b_kv);
    k_logits <<<dim3(SEQ / 32, LSPLIT), 256>>>(x);
    k_softmax<<<H, 1024>>>();
    k_y      <<<dim3(2, YSPLIT), 256>>>(x);
    k_ysum   <<<(H * DIM / 4) / 64, 256>>>();
    k_x1     <<<DIM / 8, 256>>>(W_kv, b_kv);
    k_mlp1   <<<PROJ / 8, 256>>>(W_p1, b_p1);
    k_ln     <<<1, PROJ>>>(ln_w, ln_b);
    k_mlp2   <<<DIM / 8, 256>>>(W_p2, b_p2);
    k_res    <<<(SEQ * DIM / 4) / 512, 256>>>(x, out);
}